// round 9
// baseline (speedup 1.0000x reference)
#include <cuda_runtime.h>

#define VOCABN 5000
#define NB 16
#define NS 128
#define NT 512
#define NL 257            // 2*NS + 1
#define ESTR 264          // emit scratch row stride (1056 B, 16B aligned)
#define ALPHA_W 0.2f
#define SMOOTH 0.1f
#define GB 1024           // gather blocks: NB * 64, 8 t-steps each
#define TM 255            // meet point: ll = sum_l alpha_255[l] * C(beta_256)[l]

__device__ float g_emit[NB * NT * ESTR];   // E = exp(ctc logit), 8.6 MB

// ===== kernel 1: parallel gather + exp (blank column deduped via smem) =====
__global__ __launch_bounds__(288) void gather_kernel(
    const float* __restrict__ ctc, const int* __restrict__ tgt)
{
    __shared__ float blankE[8];
    const int tid = threadIdx.x;
    const int b  = blockIdx.x >> 6;
    const int t0 = (blockIdx.x & 63) << 3;
    const float* cb = ctc + (size_t)b * NT * VOCABN;

    if (tid < 8)
        blankE[tid] = __expf(__ldg(cb + (size_t)(t0 + tid) * VOCABN));
    __syncthreads();

    if (tid < NL) {
        float* dst = g_emit + ((size_t)b * NT + t0) * ESTR + tid;
        float v[8];
        if (tid & 1) {
            int ext = __ldg(tgt + b * NS + (tid >> 1));
            const float* col = cb + ext;
            #pragma unroll
            for (int i = 0; i < 8; ++i)
                v[i] = __expf(__ldg(col + (size_t)(t0 + i) * VOCABN));
        } else {
            #pragma unroll
            for (int i = 0; i < 8; ++i) v[i] = blankE[i];
        }
        #pragma unroll
        for (int i = 0; i < 8; ++i) dst[i * ESTR] = v[i];
    }
}

// allow-2 into state x
__device__ __forceinline__ float a2_into(const int* tb, int x) {
    if ((x & 1) && x >= 3 && x < NL) {
        int e  = __ldg(tb + (x >> 1));
        int ep = __ldg(tb + (x >> 1) - 1);
        return (e != 0 && e != ep) ? 1.0f : 0.0f;
    }
    return 0.0f;
}

__device__ __forceinline__ float warp_max_pos(float m) {
    // all operands non-negative -> fp32 ordering == u32 ordering
    return __uint_as_float(__reduce_max_sync(0xffffffffu, __float_as_uint(m)));
}

// ===== kernel 2: fwd+bwd meet-in-the-middle (blocks 0..15) + att loss =====
__global__ __launch_bounds__(288) void scan_att_kernel(
    const float* __restrict__ att, const int* __restrict__ tgt,
    float* __restrict__ out)
{
    __shared__ float aS[264], bS[264];
    __shared__ float sFS, sBS;
    __shared__ float red[9];

    const int tid = threadIdx.x;
    const int blk = blockIdx.x;

    if (blk < NB) {
        const int lane = tid & 31;
        const float* eb = g_emit + (size_t)blk * NT * ESTR;
        const int*   tb = tgt + blk * NS;

        if (tid < 32) {
            // ---------------- forward warp: t = 1..255 ----------------
            float a2[8];
            #pragma unroll
            for (int j = 0; j < 8; ++j) a2[j] = a2_into(tb, 8 * lane + j);

            float v[8], v8 = 0.0f;
            #pragma unroll
            for (int j = 0; j < 8; ++j) v[j] = 0.0f;
            if (lane == 0) { v[0] = __ldg(eb + 0); v[1] = __ldg(eb + 1); }

            float4 Ea4[4], Eb4[4];
            #pragma unroll
            for (int d = 0; d < 4; ++d) {
                const float* src = eb + (size_t)(1 + d) * ESTR + 8 * lane;
                Ea4[d] = *(const float4*)src;
                Eb4[d] = *(const float4*)(src + 4);
            }

            float sF = 0.0f;
            for (int tt = 0; tt < 32; ++tt) {
                #pragma unroll
                for (int i = 0; i < 8; ++i) {
                    const int t = 1 + tt * 8 + i;
                    if (t <= TM) {
                        float4 EA = Ea4[i & 3], EB = Eb4[i & 3];
                        const int tp = t + 4;
                        if (tp <= TM) {
                            const float* src = eb + (size_t)tp * ESTR + 8 * lane;
                            Ea4[i & 3] = *(const float4*)src;
                            Eb4[i & 3] = *(const float4*)(src + 4);
                        }
                        float E8 = __shfl_sync(0xffffffffu, EA.x, 0); // blank
                        float x1 = __shfl_up_sync(0xffffffffu, v[7], 1);
                        float x2 = __shfl_up_sync(0xffffffffu, v[6], 1);
                        if (lane == 0) { x1 = 0.0f; x2 = 0.0f; }
                        float n0 = (v[0] + x1)   + a2[0] * x2;
                        float n1 = (v[1] + v[0]) + a2[1] * x1;
                        float n2 = (v[2] + v[1]) + a2[2] * v[0];
                        float n3 = (v[3] + v[2]) + a2[3] * v[1];
                        float n4 = (v[4] + v[3]) + a2[4] * v[2];
                        float n5 = (v[5] + v[4]) + a2[5] * v[3];
                        float n6 = (v[6] + v[5]) + a2[6] * v[4];
                        float n7 = (v[7] + v[6]) + a2[7] * v[5];
                        float n8 = v8 + v[7];
                        v[0] = n0 * EA.x; v[1] = n1 * EA.y;
                        v[2] = n2 * EA.z; v[3] = n3 * EA.w;
                        v[4] = n4 * EB.x; v[5] = n5 * EB.y;
                        v[6] = n6 * EB.z; v[7] = n7 * EB.w;
                        v8   = n8 * E8;
                    }
                }
                float m = v[0];
                #pragma unroll
                for (int j = 1; j < 8; ++j) m = fmaxf(m, v[j]);
                m = fmaxf(m, v8);
                m = warp_max_pos(m);
                float r = __fdividef(1.0f, m);
                #pragma unroll
                for (int j = 0; j < 8; ++j) v[j] *= r;
                v8 *= r;
                sF += __logf(m);
            }
            #pragma unroll
            for (int j = 0; j < 8; ++j) aS[8 * lane + j] = v[j];
            if (lane == 31) aS[256] = v8;
            if (lane == 0) sFS = sF;
        } else if (tid < 64) {
            // ---------------- backward warp: t = 510..256 (init at 511) ----------------
            float a2b[8];
            #pragma unroll
            for (int j = 0; j < 8; ++j) a2b[j] = a2_into(tb, 8 * lane + j + 2);

            float v[8], v8 = 0.0f;
            #pragma unroll
            for (int j = 0; j < 8; ++j) v[j] = 0.0f;
            if (lane == 31) {
                const float* e511 = eb + (size_t)511 * ESTR;
                v[7] = __ldg(e511 + 255);
                v8   = __ldg(e511 + 0);          // state 256 emission = blank
            }

            float4 Ea4[4], Eb4[4];
            #pragma unroll
            for (int d = 0; d < 4; ++d) {
                const float* src = eb + (size_t)(510 - d) * ESTR + 8 * lane;
                Ea4[d] = *(const float4*)src;
                Eb4[d] = *(const float4*)(src + 4);
            }

            float sB = 0.0f;
            for (int tt = 0; tt < 32; ++tt) {
                #pragma unroll
                for (int i = 0; i < 8; ++i) {
                    const int t = 510 - (tt * 8 + i);
                    if (t >= TM + 1) {
                        float4 EA = Ea4[i & 3], EB = Eb4[i & 3];
                        const int tp = t - 4;
                        if (tp >= TM + 1) {
                            const float* src = eb + (size_t)tp * ESTR + 8 * lane;
                            Ea4[i & 3] = *(const float4*)src;
                            Eb4[i & 3] = *(const float4*)(src + 4);
                        }
                        float E8 = __shfl_sync(0xffffffffu, EA.x, 0);
                        float x1 = __shfl_down_sync(0xffffffffu, v[0], 1); // state 8l+8
                        float x2 = __shfl_down_sync(0xffffffffu, v[1], 1); // state 8l+9
                        if (lane == 31) { x1 = v8; x2 = 0.0f; }
                        float n0 = (v[0] + v[1]) + a2b[0] * v[2];
                        float n1 = (v[1] + v[2]) + a2b[1] * v[3];
                        float n2 = (v[2] + v[3]) + a2b[2] * v[4];
                        float n3 = (v[3] + v[4]) + a2b[3] * v[5];
                        float n4 = (v[4] + v[5]) + a2b[4] * v[6];
                        float n5 = (v[5] + v[6]) + a2b[5] * v[7];
                        float n6 = (v[6] + v[7]) + a2b[6] * x1;
                        float n7 = (v[7] + x1)   + a2b[7] * x2;
                        float n8 = v8;                        // state 256: self only
                        v[0] = n0 * EA.x; v[1] = n1 * EA.y;
                        v[2] = n2 * EA.z; v[3] = n3 * EA.w;
                        v[4] = n4 * EB.x; v[5] = n5 * EB.y;
                        v[6] = n6 * EB.z; v[7] = n7 * EB.w;
                        v8   = n8 * E8;
                    }
                }
                float m = v[0];
                #pragma unroll
                for (int j = 1; j < 8; ++j) m = fmaxf(m, v[j]);
                m = fmaxf(m, v8);
                m = warp_max_pos(m);
                float r = __fdividef(1.0f, m);
                #pragma unroll
                for (int j = 0; j < 8; ++j) v[j] *= r;
                v8 *= r;
                sB += __logf(m);
            }
            #pragma unroll
            for (int j = 0; j < 8; ++j) bS[8 * lane + j] = v[j];
            if (lane == 31) { bS[256] = v8; bS[257] = 0.0f; bS[258] = 0.0f; }
            if (lane == 0) sBS = sB;
        }

        __syncthreads();

        if (tid < 32) {
            float dot = 0.0f;
            #pragma unroll
            for (int j = 0; j < 8; ++j) {
                int s = 8 * lane + j;
                float C = bS[s] + bS[s + 1] + a2_into(tb, s + 2) * bS[s + 2];
                dot += aS[s] * C;
            }
            if (lane == 31) dot += aS[256] * bS[256];
            #pragma unroll
            for (int o = 16; o > 0; o >>= 1)
                dot += __shfl_xor_sync(0xffffffffu, dot, o);
            if (lane == 0) {
                float ll = __logf(dot) + sFS + sBS;
                float lb = -ll;
                if (!(lb < 1e20f)) lb = 0.0f;      // zero_infinity (inf/nan too)
                atomicAdd(out, ((1.0f - ALPHA_W) / (float)(NB * NS)) * lb);
            }
        }
    } else {
        // ================= label-smoothing row `blk - NB` =================
        const int r = blk - NB;
        const float* row = att + (size_t)r * VOCABN;
        const int tv = __ldg(tgt + r);

        float s = 0.0f;
        const float4* row4 = (const float4*)row;
        for (int i = tid; i < VOCABN / 4; i += 288) {
            float4 v = row4[i];
            s += (v.x + v.y) + (v.z + v.w);
        }
        #pragma unroll
        for (int o = 16; o > 0; o >>= 1)
            s += __shfl_down_sync(0xffffffffu, s, o);
        const int wid = tid >> 5, lane = tid & 31;
        if (lane == 0) red[wid] = s;
        __syncthreads();
        if (tid == 0) {
            float total = 0.0f;
            #pragma unroll
            for (int w = 0; w < 9; ++w) total += red[w];
            float tl = __ldg(row + tv);
            const float conf = 1.0f - SMOOTH;
            const float off  = SMOOTH / (float)(VOCABN - 1);
            float per_row = -(off * total + (conf - off) * tl);
            atomicAdd(out, (ALPHA_W / 2048.0f) * per_row);
        }
    }
}

extern "C" void kernel_launch(void* const* d_in, const int* in_sizes, int n_in,
                              void* d_out, int out_size) {
    const float* att = (const float*)d_in[0];
    const float* ctc = (const float*)d_in[1];
    const int*   tgt = (const int*)d_in[2];
    float* out = (float*)d_out;

    cudaMemsetAsync(out, 0, sizeof(float));
    gather_kernel<<<GB, 288>>>(ctc, tgt);
    scan_att_kernel<<<NB + NB * NS, 288>>>(att, tgt, out);
}

// round 11
// speedup vs baseline: 2.7149x; 2.7149x over previous
#include <cuda_runtime.h>
#include <cuda_pipeline.h>

#define VOCABN 5000
#define NB 16
#define NS 128
#define NT 512
#define NL 257            // 2*NS + 1
#define ESTR 264          // emit scratch row stride in g_emit
#define RS 256            // ring slot stride (256 floats = 1KB)
#define ALPHA_W 0.2f
#define SMOOTH 0.1f
#define DPTH 8            // cp.async ring depth
#define GB 1024           // gather blocks: NB * 64, 8 t-steps each
#define TM 255            // meet point

__device__ float g_emit[NB * NT * ESTR];   // E = exp(ctc logit), 8.6 MB

// ===== kernel 1: parallel gather + exp (blank column deduped) =====
__global__ __launch_bounds__(288) void gather_kernel(
    const float* __restrict__ ctc, const int* __restrict__ tgt)
{
    __shared__ float blankE[8];
    const int tid = threadIdx.x;
    const int b  = blockIdx.x >> 6;
    const int t0 = (blockIdx.x & 63) << 3;
    const float* cb = ctc + (size_t)b * NT * VOCABN;

    if (tid < 8)
        blankE[tid] = __expf(__ldg(cb + (size_t)(t0 + tid) * VOCABN));
    __syncthreads();

    if (tid < NL) {
        float* dst = g_emit + ((size_t)b * NT + t0) * ESTR + tid;
        float v[8];
        if (tid & 1) {
            int ext = __ldg(tgt + b * NS + (tid >> 1));
            const float* col = cb + ext;
            #pragma unroll
            for (int i = 0; i < 8; ++i)
                v[i] = __expf(__ldg(col + (size_t)(t0 + i) * VOCABN));
        } else {
            #pragma unroll
            for (int i = 0; i < 8; ++i) v[i] = blankE[i];
        }
        #pragma unroll
        for (int i = 0; i < 8; ++i) dst[i * ESTR] = v[i];
    }
}

__device__ __forceinline__ float a2_into(const int* tb, int x) {
    if ((x & 1) && x >= 3 && x < NL) {
        int e  = __ldg(tb + (x >> 1));
        int ep = __ldg(tb + (x >> 1) - 1);
        return (e != 0 && e != ep) ? 1.0f : 0.0f;
    }
    return 0.0f;
}

__device__ __forceinline__ float warp_max_pos(float m) {
    // all operands non-negative -> fp32 ordering == u32 ordering
    return __uint_as_float(__reduce_max_sync(0xffffffffu, __float_as_uint(m)));
}

// ===== kernel 2: fwd+bwd meet-in-the-middle (blocks 0..15) + att loss =====
__global__ __launch_bounds__(288) void scan_att_kernel(
    const float* __restrict__ att, const int* __restrict__ tgt,
    float* __restrict__ out)
{
    __shared__ __align__(16) float ringF[DPTH * RS];
    __shared__ __align__(16) float ringB[DPTH * RS];
    __shared__ float aS[264], bS[264];
    __shared__ float sFS, sBS;
    __shared__ float red[9];

    const int tid = threadIdx.x;
    const int blk = blockIdx.x;

    if (blk < NB) {
        const int lane = tid & 31;
        const float* eb = g_emit + (size_t)blk * NT * ESTR;
        const int*   tb = tgt + blk * NS;

        if (tid < 32) {
            // ---------------- forward warp: t = 1..255 ----------------
            float a2[8];
            #pragma unroll
            for (int j = 0; j < 8; ++j) a2[j] = a2_into(tb, 8 * lane + j);

            float v[8], v8 = 0.0f;
            #pragma unroll
            for (int j = 0; j < 8; ++j) v[j] = 0.0f;
            if (lane == 0) { v[0] = __ldg(eb + 0); v[1] = __ldg(eb + 1); }

            #pragma unroll
            for (int d = 0; d < DPTH; ++d) {
                const float* src = eb + (size_t)(1 + d) * ESTR + 8 * lane;
                __pipeline_memcpy_async(&ringF[d * RS + 8 * lane],     src,     16);
                __pipeline_memcpy_async(&ringF[d * RS + 8 * lane + 4], src + 4, 16);
                __pipeline_commit();
            }
            __pipeline_wait_prior(DPTH - 2);            // steps 1,2 landed
            float4 EAr = *(const float4*)&ringF[8 * lane];       // E_1
            float4 EBr = *(const float4*)&ringF[8 * lane + 4];

            float sF = 0.0f;
            for (int tt = 0; tt < 32; ++tt) {
                #pragma unroll
                for (int i = 0; i < 8; ++i) {
                    const int t = 1 + tt * 8 + i;
                    if (t <= TM) {
                        float4 EA = EAr, EB = EBr;       // E_t
                        const int tp = t + DPTH;
                        if (tp <= TM) {
                            const float* src = eb + (size_t)tp * ESTR + 8 * lane;
                            __pipeline_memcpy_async(&ringF[i * RS + 8 * lane],     src,     16);
                            __pipeline_memcpy_async(&ringF[i * RS + 8 * lane + 4], src + 4, 16);
                        }
                        __pipeline_commit();
                        __pipeline_wait_prior(DPTH - 2); // data through t+2 landed
                        // preload E_{t+1} (slot (i+1)&7); overlaps with compute below
                        const float* rs = &ringF[((i + 1) & 7) * RS + 8 * lane];
                        EAr = *(const float4*)rs;
                        EBr = *(const float4*)(rs + 4);

                        float E8 = __shfl_sync(0xffffffffu, EA.x, 0); // blank
                        float x1 = __shfl_up_sync(0xffffffffu, v[7], 1);
                        float x2 = __shfl_up_sync(0xffffffffu, v[6], 1);
                        if (lane == 0) { x1 = 0.0f; x2 = 0.0f; }
                        float n0 = (v[0] + x1)   + a2[0] * x2;
                        float n1 = (v[1] + v[0]) + a2[1] * x1;
                        float n2 = (v[2] + v[1]) + a2[2] * v[0];
                        float n3 = (v[3] + v[2]) + a2[3] * v[1];
                        float n4 = (v[4] + v[3]) + a2[4] * v[2];
                        float n5 = (v[5] + v[4]) + a2[5] * v[3];
                        float n6 = (v[6] + v[5]) + a2[6] * v[4];
                        float n7 = (v[7] + v[6]) + a2[7] * v[5];
                        float n8 = v8 + v[7];
                        v[0] = n0 * EA.x; v[1] = n1 * EA.y;
                        v[2] = n2 * EA.z; v[3] = n3 * EA.w;
                        v[4] = n4 * EB.x; v[5] = n5 * EB.y;
                        v[6] = n6 * EB.z; v[7] = n7 * EB.w;
                        v8   = n8 * E8;
                    }
                }
                float m01 = fmaxf(v[0], v[1]), m23 = fmaxf(v[2], v[3]);
                float m45 = fmaxf(v[4], v[5]), m67 = fmaxf(v[6], v[7]);
                float m = fmaxf(fmaxf(m01, m23), fmaxf(fmaxf(m45, m67), v8));
                m = warp_max_pos(m);
                float r = __fdividef(1.0f, m);
                #pragma unroll
                for (int j = 0; j < 8; ++j) v[j] *= r;
                v8 *= r;
                sF += __logf(m);
            }
            #pragma unroll
            for (int j = 0; j < 8; ++j) aS[8 * lane + j] = v[j];
            if (lane == 31) aS[256] = v8;
            if (lane == 0) sFS = sF;
        } else if (tid < 64) {
            // ---------------- backward warp: t = 510..256 (init at 511) ----------------
            float a2b[8];
            #pragma unroll
            for (int j = 0; j < 8; ++j) a2b[j] = a2_into(tb, 8 * lane + j + 2);

            float v[8], v8 = 0.0f;
            #pragma unroll
            for (int j = 0; j < 8; ++j) v[j] = 0.0f;
            if (lane == 31) {
                const float* e511 = eb + (size_t)511 * ESTR;
                v[7] = __ldg(e511 + 255);
                v8   = __ldg(e511 + 0);          // state 256 emission = blank
            }

            #pragma unroll
            for (int d = 0; d < DPTH; ++d) {
                const float* src = eb + (size_t)(510 - d) * ESTR + 8 * lane;
                __pipeline_memcpy_async(&ringB[d * RS + 8 * lane],     src,     16);
                __pipeline_memcpy_async(&ringB[d * RS + 8 * lane + 4], src + 4, 16);
                __pipeline_commit();
            }
            __pipeline_wait_prior(DPTH - 2);            // steps 510,509 landed
            float4 EAr = *(const float4*)&ringB[8 * lane];       // E_510
            float4 EBr = *(const float4*)&ringB[8 * lane + 4];

            float sB = 0.0f;
            for (int tt = 0; tt < 32; ++tt) {
                #pragma unroll
                for (int i = 0; i < 8; ++i) {
                    const int t = 510 - (tt * 8 + i);
                    if (t >= TM + 1) {
                        float4 EA = EAr, EB = EBr;       // E_t
                        const int tp = t - DPTH;
                        if (tp >= TM + 1) {
                            const float* src = eb + (size_t)tp * ESTR + 8 * lane;
                            __pipeline_memcpy_async(&ringB[i * RS + 8 * lane],     src,     16);
                            __pipeline_memcpy_async(&ringB[i * RS + 8 * lane + 4], src + 4, 16);
                        }
                        __pipeline_commit();
                        __pipeline_wait_prior(DPTH - 2);
                        const float* rs = &ringB[((i + 1) & 7) * RS + 8 * lane];
                        EAr = *(const float4*)rs;        // E_{t-1}
                        EBr = *(const float4*)(rs + 4);

                        float E8 = __shfl_sync(0xffffffffu, EA.x, 0);
                        float x1 = __shfl_down_sync(0xffffffffu, v[0], 1); // state 8l+8
                        float x2 = __shfl_down_sync(0xffffffffu, v[1], 1); // state 8l+9
                        if (lane == 31) { x1 = v8; x2 = 0.0f; }
                        float n0 = (v[0] + v[1]) + a2b[0] * v[2];
                        float n1 = (v[1] + v[2]) + a2b[1] * v[3];
                        float n2 = (v[2] + v[3]) + a2b[2] * v[4];
                        float n3 = (v[3] + v[4]) + a2b[3] * v[5];
                        float n4 = (v[4] + v[5]) + a2b[4] * v[6];
                        float n5 = (v[5] + v[6]) + a2b[5] * v[7];
                        float n6 = (v[6] + v[7]) + a2b[6] * x1;
                        float n7 = (v[7] + x1)   + a2b[7] * x2;
                        float n8 = v8;                        // state 256: self only
                        v[0] = n0 * EA.x; v[1] = n1 * EA.y;
                        v[2] = n2 * EA.z; v[3] = n3 * EA.w;
                        v[4] = n4 * EB.x; v[5] = n5 * EB.y;
                        v[6] = n6 * EB.z; v[7] = n7 * EB.w;
                        v8   = n8 * E8;
                    }
                }
                float m01 = fmaxf(v[0], v[1]), m23 = fmaxf(v[2], v[3]);
                float m45 = fmaxf(v[4], v[5]), m67 = fmaxf(v[6], v[7]);
                float m = fmaxf(fmaxf(m01, m23), fmaxf(fmaxf(m45, m67), v8));
                m = warp_max_pos(m);
                float r = __fdividef(1.0f, m);
                #pragma unroll
                for (int j = 0; j < 8; ++j) v[j] *= r;
                v8 *= r;
                sB += __logf(m);
            }
            #pragma unroll
            for (int j = 0; j < 8; ++j) bS[8 * lane + j] = v[j];
            if (lane == 31) { bS[256] = v8; bS[257] = 0.0f; bS[258] = 0.0f; }
            if (lane == 0) sBS = sB;
        }

        __syncthreads();

        if (tid < 32) {
            float dot = 0.0f;
            #pragma unroll
            for (int j = 0; j < 8; ++j) {
                int s = 8 * lane + j;
                float C = bS[s] + bS[s + 1] + a2_into(tb, s + 2) * bS[s + 2];
                dot += aS[s] * C;
            }
            if (lane == 31) dot += aS[256] * bS[256];
            #pragma unroll
            for (int o = 16; o > 0; o >>= 1)
                dot += __shfl_xor_sync(0xffffffffu, dot, o);
            if (lane == 0) {
                float ll = __logf(dot) + sFS + sBS;
                float lb = -ll;
                if (!(lb < 1e20f)) lb = 0.0f;      // zero_infinity (inf/nan too)
                atomicAdd(out, ((1.0f - ALPHA_W) / (float)(NB * NS)) * lb);
            }
        }
    } else {
        // ================= label-smoothing row `blk - NB` =================
        const int r = blk - NB;
        const float* row = att + (size_t)r * VOCABN;
        const int tv = __ldg(tgt + r);

        float s = 0.0f;
        const float4* row4 = (const float4*)row;
        for (int i = tid; i < VOCABN / 4; i += 288) {
            float4 v = row4[i];
            s += (v.x + v.y) + (v.z + v.w);
        }
        #pragma unroll
        for (int o = 16; o > 0; o >>= 1)
            s += __shfl_down_sync(0xffffffffu, s, o);
        const int wid = tid >> 5, lane = tid & 31;
        if (lane == 0) red[wid] = s;
        __syncthreads();
        if (tid == 0) {
            float total = 0.0f;
            #pragma unroll
            for (int w = 0; w < 9; ++w) total += red[w];
            float tl = __ldg(row + tv);
            const float conf = 1.0f - SMOOTH;
            const float off  = SMOOTH / (float)(VOCABN - 1);
            float per_row = -(off * total + (conf - off) * tl);
            atomicAdd(out, (ALPHA_W / 2048.0f) * per_row);
        }
    }
}

extern "C" void kernel_launch(void* const* d_in, const int* in_sizes, int n_in,
                              void* d_out, int out_size) {
    const float* att = (const float*)d_in[0];
    const float* ctc = (const float*)d_in[1];
    const int*   tgt = (const int*)d_in[2];
    float* out = (float*)d_out;

    cudaMemsetAsync(out, 0, sizeof(float));
    gather_kernel<<<GB, 288>>>(ctc, tgt);
    scan_att_kernel<<<NB + NB * NS, 288>>>(att, tgt, out);
}